// round 15
// baseline (speedup 1.0000x reference)
#include <cuda_runtime.h>
#include <cstdint>

#define THREADS 512                 // 16 identical mixed-role warps
#define IN_DIM  2304
#define OUT_DIM 576
#define BATCH   16384
#define NCTA    148

#define ROWS_B  8                   // rows per warp buffer
#define NBUF    2                   // ring depth per warp
#define WROW_F4 40                  // f4 per row per warp (36 data + pads)
#define WROW_B  (WROW_F4 * 16)      // 640
#define WBUF_B  (ROWS_B * WROW_B)   // 5120
#define WREG_B  (NBUF * WBUF_B)     // 10240
#define SMEM_BYTES (16 * WREG_B)    // 163840

// Per-warp smem row layout (f4 index):
//   [0,16)  seg3 group g          (x f4 320+16g+j)
//   [17,25) seg2 group 2g         (x f4 64+16g+j)
//   [27,35) seg2 group 2g+1       (x f4 72+16g+j)
//   [36,40) seg1 group g          (x f4 4g+j)
// Offsets 17/27/36 chosen so the distinct f4 touched per k4 step never share
// a bank quad -> every LDS step is a single wavefront (phase A is a 16-lane
// broadcast: only 2 distinct f4 per step).

__device__ __forceinline__ void cpa16(uint32_t daddr, const void* src) {
    asm volatile("cp.async.cg.shared.global [%0], [%1], 16;\n" :: "r"(daddr), "l"(src));
}

#define FMA2(acc, a, b) \
    asm("fma.rn.f32x2 %0, %1, %2, %0;" : "+l"(acc) : "l"(a), "l"(b))
#define PACK2(p, lo, hi) \
    asm("mov.b64 %0, {%1, %2};" : "=l"(p) : "f"(lo), "f"(hi))
#define LDS_V2B64(lo, hi, addr) \
    asm("ld.shared.v2.b64 {%0, %1}, [%2];" : "=l"(lo), "=l"(hi) : "r"(addr))

__device__ __forceinline__ float hsum2(uint64_t p) {
    float lo, hi;
    asm("mov.b64 {%0, %1}, %2;" : "=f"(lo), "=f"(hi) : "l"(p));
    return lo + hi;
}

extern "C" __global__ void __launch_bounds__(THREADS, 1)
tet_kernel(const float* __restrict__ x, const float* __restrict__ w,
           const float* __restrict__ bias, float* __restrict__ out)
{
    extern __shared__ __align__(16) char Xs[];   // [16 warps][NBUF][ROWS_B][640B]

    const int tid  = threadIdx.x;
    const int wid  = tid >> 5;       // warp = slice index g
    const int lane = tid & 31;
    const int g    = wid;
    const int bid  = blockIdx.x;
    const int h    = lane & 1;       // K-half parity (partner = lane^1)
    const int c    = lane >> 1;      // column index within phase (0..15)

    // row partition: 16384 = 148*110 + 104
    const int row0  = bid * 110 + (bid < 104 ? bid : 104);
    const int nrows = 110 + (bid < 104 ? 1 : 0);
    const int nch   = (nrows + ROWS_B - 1) / ROWS_B;   // 14

    // ---------------- W into registers (K-interleave: k = 8*k4 + 4*h + i) ----
    uint64_t wA[16];   // seg3: col c, 32 k-half values
    uint64_t wB[8];    // seg2: col c of groups {2g,2g+1}, 16 k-half values
    uint64_t wC[4];    // seg1: col (c&3), 8 k-half values (replicated x4 lanes)
    {
        const int a3 = 9216 + g * 1024 + c;               // seg3 [k][16]
        #pragma unroll
        for (int k4 = 0; k4 < 8; k4++)
            #pragma unroll
            for (int j = 0; j < 2; j++) {
                int k = 8 * k4 + 4 * h + 2 * j;
                PACK2(wA[2*k4+j], w[a3 + k * 16], w[a3 + (k+1) * 16]);
            }
        const int G2 = 2 * g + (c >> 3);
        const int a2 = 1024 + G2 * 256 + (c & 7);          // seg2 [k][8]
        #pragma unroll
        for (int k4 = 0; k4 < 4; k4++)
            #pragma unroll
            for (int j = 0; j < 2; j++) {
                int k = 8 * k4 + 4 * h + 2 * j;
                PACK2(wB[2*k4+j], w[a2 + k * 8], w[a2 + (k+1) * 8]);
            }
        const int a1 = g * 64 + (c & 3);                   // seg1 [k][4]
        #pragma unroll
        for (int k4 = 0; k4 < 2; k4++)
            #pragma unroll
            for (int j = 0; j < 2; j++) {
                int k = 8 * k4 + 4 * h + 2 * j;
                PACK2(wC[2*k4+j], w[a1 + k * 4], w[a1 + (k+1) * 4]);
            }
    }
    const int colA = 320 + 16 * g + c;
    const int colB = 64 + 16 * g + c;
    const int colC = 4 * g + (c & 3);
    const float bA = bias[colA], bB = bias[colB], bC = bias[colC];

    // ---------------- staging setup (warp-private ring) ----------------
    const uint32_t wbase = (uint32_t)__cvta_generic_to_shared(Xs) + wid * WREG_B;
    // span 0: 32 lanes, 1 f4 each
    const int srcF0 = (lane < 16) ? (320 + 16 * g + lane) : (64 + 16 * g + (lane - 16));
    const int dstF0 = (lane < 16) ? lane : ((lane < 24) ? 17 + (lane - 16) : 27 + (lane - 24));
    // span 1: lanes 0-3 only
    const int srcF1 = 4 * g + lane;
    const uint32_t dst0 = wbase + (uint32_t)dstF0 * 16;
    const uint32_t dst1 = wbase + (uint32_t)(36 + lane) * 16;
    const char* src0 = (const char*)(x + (size_t)row0 * IN_DIM) + (size_t)srcF0 * 16;
    const char* src1 = (const char*)(x + (size_t)row0 * IN_DIM) + (size_t)srcF1 * 16;

    auto stage = [&](int i) {
        const uint32_t bo = (uint32_t)(i & (NBUF - 1)) * WBUF_B;
        const size_t so = (size_t)i * (ROWS_B * IN_DIM * 4);
        const int umax = nrows - i * ROWS_B;
        #pragma unroll
        for (int r = 0; r < ROWS_B; r++) {
            if (r < umax) {
                cpa16(dst0 + bo + r * WROW_B, src0 + so + (size_t)r * (IN_DIM * 4));
                if (lane < 4) cpa16(dst1 + bo + r * WROW_B, src1 + so + (size_t)r * (IN_DIM * 4));
            }
        }
    };

    // compute read bases (f4 step per k4 = 2 f4 = 32B)
    const uint32_t rdA = wbase + (uint32_t)h * 16;                       // f4 2k4+h
    const uint32_t rdB = wbase + (uint32_t)(((c >> 3) ? 27 : 17) + h) * 16;
    const uint32_t rdC = wbase + (uint32_t)(36 + h) * 16;

    stage(0);
    asm volatile("cp.async.commit_group;\n");

    for (int i = 0; i < nch; i++) {
        if (i + 1 < nch) stage(i + 1);
        asm volatile("cp.async.commit_group;\n");
        asm volatile("cp.async.wait_group 1;\n");     // drain chunk i
        __syncwarp();

        const uint32_t bo = (uint32_t)(i & (NBUF - 1)) * WBUF_B;
        const int rmax = min(ROWS_B, nrows - i * ROWS_B);
        float* ob = out + (size_t)(row0 + i * ROWS_B) * OUT_DIM;

        #pragma unroll
        for (int r = 0; r < ROWS_B; r += 2) {
            if (r >= rmax) break;
            const uint32_t r0 = bo + (uint32_t)r * WROW_B;
            const uint32_t r1 = r0 + WROW_B;          // smem in-bounds; store guarded

            uint64_t sA0 = 0, sA1 = 0, sB0 = 0, sB1 = 0, sC0 = 0, sC1 = 0;
            // phase A: seg3 (broadcast LDS: 2 distinct f4 per step)
            #pragma unroll
            for (int k4 = 0; k4 < 8; k4++) {
                uint64_t u01, u23, v01, v23;
                LDS_V2B64(u01, u23, rdA + r0 + k4 * 32);
                LDS_V2B64(v01, v23, rdA + r1 + k4 * 32);
                FMA2(sA0, u01, wA[2*k4]); FMA2(sA0, u23, wA[2*k4+1]);
                FMA2(sA1, v01, wA[2*k4]); FMA2(sA1, v23, wA[2*k4+1]);
            }
            // phase B: seg2
            #pragma unroll
            for (int k4 = 0; k4 < 4; k4++) {
                uint64_t u01, u23, v01, v23;
                LDS_V2B64(u01, u23, rdB + r0 + k4 * 32);
                LDS_V2B64(v01, v23, rdB + r1 + k4 * 32);
                FMA2(sB0, u01, wB[2*k4]); FMA2(sB0, u23, wB[2*k4+1]);
                FMA2(sB1, v01, wB[2*k4]); FMA2(sB1, v23, wB[2*k4+1]);
            }
            // phase C: seg1 (computed by all lanes, stored by lanes 0,2,4,6)
            #pragma unroll
            for (int k4 = 0; k4 < 2; k4++) {
                uint64_t u01, u23, v01, v23;
                LDS_V2B64(u01, u23, rdC + r0 + k4 * 32);
                LDS_V2B64(v01, v23, rdC + r1 + k4 * 32);
                FMA2(sC0, u01, wC[2*k4]); FMA2(sC0, u23, wC[2*k4+1]);
                FMA2(sC1, v01, wC[2*k4]); FMA2(sC1, v23, wC[2*k4+1]);
            }

            float fA0 = hsum2(sA0), fA1 = hsum2(sA1);
            float fB0 = hsum2(sB0), fB1 = hsum2(sB1);
            float fC0 = hsum2(sC0), fC1 = hsum2(sC1);
            fA0 += __shfl_xor_sync(0xffffffffu, fA0, 1);
            fA1 += __shfl_xor_sync(0xffffffffu, fA1, 1);
            fB0 += __shfl_xor_sync(0xffffffffu, fB0, 1);
            fB1 += __shfl_xor_sync(0xffffffffu, fB1, 1);
            fC0 += __shfl_xor_sync(0xffffffffu, fC0, 1);
            fC1 += __shfl_xor_sync(0xffffffffu, fC1, 1);

            if (h == 0) {
                float* o0 = ob + (size_t)r * OUT_DIM;
                o0[colA] = fA0 + bA;
                o0[colB] = fB0 + bB;
                if (lane < 8) o0[colC] = fC0 + bC;
                if (r + 1 < rmax) {
                    float* o1 = o0 + OUT_DIM;
                    o1[colA] = fA1 + bA;
                    o1[colB] = fB1 + bB;
                    if (lane < 8) o1[colC] = fC1 + bC;
                }
            }
        }
        __syncwarp();   // lanes done reading buf i before re-stage next iter
    }
}

extern "C" void kernel_launch(void* const* d_in, const int* in_sizes, int n_in,
                              void* d_out, int out_size)
{
    const float* x    = (const float*)d_in[0];
    const float* wflt = (const float*)d_in[1];
    const float* bias = (const float*)d_in[2];
    float* out        = (float*)d_out;

    cudaFuncSetAttribute(tet_kernel, cudaFuncAttributeMaxDynamicSharedMemorySize, SMEM_BYTES);
    tet_kernel<<<NCTA, THREADS, SMEM_BYTES>>>(x, wflt, bias, out);
}

// round 17
// speedup vs baseline: 1.0412x; 1.0412x over previous
#include <cuda_runtime.h>
#include <cstdint>

#define THREADS 832                 // 26 warps: 16 seg3(quarter-K), 8 seg2, 2 seg1
#define IN_DIM  2304
#define OUT_DIM 576
#define BATCH   16384
#define RS4     688                 // padded row stride in float4
#define CHUNK   8                   // rows per chunk
#define NCTA    148
#define XBUF_F4 (CHUNK * RS4)       // 5504 float4 per buffer
#define SMEM_BYTES (2 * XBUF_F4 * 16)   // 176128

// Padded smem row layout (float4 indices within one x row) — same as R8:
//   seg1: 16 groups, stride 5  -> [0, 80)
//   seg2: 32 groups, stride 10 -> [80, 400)
//   seg3: 16 groups, stride 18 -> [400, 688)
__device__ __forceinline__ int pad_map(int f) {
    if (f < 64)  return f + (f >> 2);
    if (f < 320) return 80 + (f - 64) + (((f - 64) >> 3) << 1);
    return 400 + (f - 320) + (((f - 320) >> 4) << 1);
}

__device__ __forceinline__ void cpa16(uint32_t daddr, const void* src) {
    asm volatile("cp.async.cg.shared.global [%0], [%1], 16;\n" :: "r"(daddr), "l"(src));
}

#define FMA2(acc, a, b) \
    asm("fma.rn.f32x2 %0, %1, %2, %0;" : "+l"(acc) : "l"(a), "l"(b))
#define PACK2(p, lo, hi) \
    asm("mov.b64 %0, {%1, %2};" : "=l"(p) : "f"(lo), "f"(hi))
#define LDS_V2B64(lo, hi, addr) \
    asm("ld.shared.v2.b64 {%0, %1}, [%2];" : "=l"(lo), "=l"(hi) : "r"(addr))

__device__ __forceinline__ float hsum2(uint64_t p) {
    float lo, hi;
    asm("mov.b64 {%0, %1}, %2;" : "=f"(lo), "=f"(hi) : "l"(p));
    return lo + hi;
}

// Two rows x two columns, this lane's K-slice: N4 LDS.128 per row, 4*N4 FFMA2 per row.
#define DOTPAIR2(N4, STEP)                                                   \
    {                                                                        \
        _Pragma("unroll")                                                    \
        for (int k4 = 0; k4 < (N4); k4++) {                                  \
            uint64_t u01, u23, v01, v23;                                     \
            LDS_V2B64(u01, u23, a0 + k4 * (STEP));                           \
            LDS_V2B64(v01, v23, a1 + k4 * (STEP));                           \
            FMA2(sA0, u01, wA2[2*k4]); FMA2(sA0, u23, wA2[2*k4+1]);          \
            FMA2(sB0, u01, wB2[2*k4]); FMA2(sB0, u23, wB2[2*k4+1]);          \
            FMA2(sA1, v01, wA2[2*k4]); FMA2(sA1, v23, wA2[2*k4+1]);          \
            FMA2(sB1, v01, wB2[2*k4]); FMA2(sB1, v23, wB2[2*k4+1]);          \
        }                                                                    \
    }

extern "C" __global__ void __launch_bounds__(THREADS, 1)
tet_kernel(const float* __restrict__ x, const float* __restrict__ w,
           const float* __restrict__ bias, float* __restrict__ out)
{
    extern __shared__ __align__(16) float4 Xs[];          // [2][CHUNK][RS4]

    const int tid = threadIdx.x;
    const int bid = blockIdx.x;

    // row partition: 16384 = 148*110 + 104
    const int row0  = bid * 110 + (bid < 104 ? bid : 104);
    const int nrows = 110 + (bid < 104 ? 1 : 0);
    const int nchunks = (nrows + CHUNK - 1) / CHUNK;      // 14

    // ---- role setup ----
    // tid < 512  : seg3, QUARTER-K. quad lane q = tid&3 owns f4 {4k4+q},
    //              i.e. k = 16*k4 + 4*q + (0..3); nk4 = 4; LDS step 64B.
    // 512..767   : seg2, HALF-K (R8 mapping). h = tid&1, k = 8*k4+4*h+(0..3);
    //              nk4 = 4; LDS step 32B.
    // 768..831   : seg1, HALF-K. nk4 = 2; step 32B.
    uint64_t wA2[8], wB2[8];
    int xoff, myCol, role;   // role: 0=seg3q, 1=seg2h, 2=seg1h
    int q = tid & 3, h = tid & 1;
    if (tid < 512) {
        role = 0;
        const int p = tid >> 2, g3 = p >> 3, cp = p & 7;
        const int base = 9216 + g3 * 1024 + cp;
        #pragma unroll
        for (int k4 = 0; k4 < 4; k4++)
            #pragma unroll
            for (int j = 0; j < 2; j++) {
                int k = 16 * k4 + 4 * q + 2 * j;
                PACK2(wA2[2*k4+j], w[base + k * 16],     w[base + (k+1) * 16]);
                PACK2(wB2[2*k4+j], w[base + k * 16 + 8], w[base + (k+1) * 16 + 8]);
            }
        xoff = 400 + 18 * g3;
        const int colA = 320 + 16 * g3 + cp;
        myCol = (q == 1) ? colA + 8 : colA;       // q=0 -> colA, q=1 -> colB
    } else if (tid < 768) {
        role = 1;
        const int p = (tid - 512) >> 1, g2 = p >> 2, cp2 = p & 3;
        const int base = 1024 + g2 * 256 + cp2;
        #pragma unroll
        for (int k4 = 0; k4 < 4; k4++)
            #pragma unroll
            for (int j = 0; j < 2; j++) {
                int k = 8 * k4 + 4 * h + 2 * j;
                PACK2(wA2[2*k4+j], w[base + k * 8],     w[base + (k+1) * 8]);
                PACK2(wB2[2*k4+j], w[base + k * 8 + 4], w[base + (k+1) * 8 + 4]);
            }
        xoff = 80 + 10 * g2;
        const int colA = 64 + 8 * g2 + cp2;
        myCol = h ? colA + 4 : colA;
    } else {
        role = 2;
        const int p = (tid - 768) >> 1, g1 = p >> 1, cp1 = p & 1;
        const int base = g1 * 64 + cp1;
        #pragma unroll
        for (int k4 = 0; k4 < 2; k4++)
            #pragma unroll
            for (int j = 0; j < 2; j++) {
                int k = 8 * k4 + 4 * h + 2 * j;
                PACK2(wA2[2*k4+j], w[base + k * 4],     w[base + (k+1) * 4]);
                PACK2(wB2[2*k4+j], w[base + k * 4 + 2], w[base + (k+1) * 4 + 2]);
            }
        xoff = 5 * g1;
        const int colA = 4 * g1 + cp1;
        myCol = h ? colA + 2 : colA;
    }
    const float myBias = bias[myCol];

    // ---- staging: tid<576 stage f=tid, r=u (static addresses) ----
    const uint32_t xsAddr = (uint32_t)__cvta_generic_to_shared(Xs);
    const bool stager = tid < 576;
    const uint32_t dstPad = xsAddr + (uint32_t)pad_map(stager ? tid : 0) * 16;
    const char* srcBase = (const char*)(x + (size_t)row0 * IN_DIM) + (size_t)tid * 16;

    auto stage = [&](int cc) {
        if (!stager) return;
        const uint32_t d0 = dstPad + (uint32_t)(cc & 1) * (XBUF_F4 * 16);
        const char* s0 = srcBase + (size_t)cc * (CHUNK * IN_DIM * 4);
        const int umax = min(CHUNK, nrows - cc * CHUNK);
        #pragma unroll
        for (int u = 0; u < CHUNK; u++)
            if (u < umax) cpa16(d0 + u * (RS4 * 16), s0 + (size_t)u * (IN_DIM * 4));
    };

    // compute read base: seg3q lane reads f4 xoff + 4k4 + q (step 64B);
    // seg2/seg1 lane reads f4 xoff + 2k4 + h (step 32B).
    const uint32_t myXBase = xsAddr +
        (uint32_t)(xoff + (role == 0 ? q : h)) * 16;

    stage(0);
    asm volatile("cp.async.commit_group;\n");

    for (int c = 0; c < nchunks; c++) {
        asm volatile("cp.async.wait_group 0;\n");
        __syncthreads();   // chunk-c visible; compute(c-1) reads done before reuse
        if (c + 1 < nchunks) {
            stage(c + 1);
            asm volatile("cp.async.commit_group;\n");
        }

        const uint32_t bufAddr = myXBase + (uint32_t)(c & 1) * (XBUF_F4 * 16);
        const int rmax = min(CHUNK, nrows - c * CHUNK);
        float* ob = out + (size_t)(row0 + c * CHUNK) * OUT_DIM;

        #pragma unroll
        for (int r = 0; r < CHUNK; r += 2) {
            if (r >= rmax) break;
            const uint32_t a0 = bufAddr + (uint32_t)r * (RS4 * 16);
            const uint32_t a1 = a0 + (RS4 * 16);   // smem in-bounds; store guarded
            uint64_t sA0 = 0, sB0 = 0, sA1 = 0, sB1 = 0;
            if (role == 0)      DOTPAIR2(4, 64)
            else if (role == 1) DOTPAIR2(4, 32)
            else                DOTPAIR2(2, 32)

            float fA0 = hsum2(sA0), fB0 = hsum2(sB0);
            float fA1 = hsum2(sA1), fB1 = hsum2(sB1);
            // merge partner lane (half-K pairs: full; quarter-K: halves {q,q^1})
            fA0 += __shfl_xor_sync(0xffffffffu, fA0, 1);
            fB0 += __shfl_xor_sync(0xffffffffu, fB0, 1);
            fA1 += __shfl_xor_sync(0xffffffffu, fA1, 1);
            fB1 += __shfl_xor_sync(0xffffffffu, fB1, 1);

            float r0v, r1v;
            bool doStore;
            if (role == 0) {
                // quarter-K: select column by q parity, merge remaining half
                float s0 = (q & 1) ? fB0 : fA0;
                float s1 = (q & 1) ? fB1 : fA1;
                s0 += __shfl_xor_sync(0xffffffffu, s0, 2);
                s1 += __shfl_xor_sync(0xffffffffu, s1, 2);
                r0v = s0 + myBias;
                r1v = s1 + myBias;
                doStore = (q < 2);
            } else {
                r0v = (h ? fB0 : fA0) + myBias;
                r1v = (h ? fB1 : fA1) + myBias;
                doStore = true;
            }
            if (doStore) {
                ob[(size_t)r * OUT_DIM + myCol] = r0v;
                if (r + 1 < rmax) ob[(size_t)(r + 1) * OUT_DIM + myCol] = r1v;
            }
        }
    }
}

extern "C" void kernel_launch(void* const* d_in, const int* in_sizes, int n_in,
                              void* d_out, int out_size)
{
    const float* x    = (const float*)d_in[0];
    const float* wflt = (const float*)d_in[1];
    const float* bias = (const float*)d_in[2];
    float* out        = (float*)d_out;

    cudaFuncSetAttribute(tet_kernel, cudaFuncAttributeMaxDynamicSharedMemorySize, SMEM_BYTES);
    tet_kernel<<<NCTA, THREADS, SMEM_BYTES>>>(x, wflt, bias, out);
}